// round 4
// baseline (speedup 1.0000x reference)
#include <cuda_runtime.h>
#include <math.h>

#define BB 8
#define LLEN 1024
#define DMODEL 1024
#define NH 16
#define DHEAD 64

// ---------------- static scratch (no allocations allowed) ----------------
static __device__ float g_Q[(size_t)BB * NH * LLEN * DHEAD];     // 32 MB
static __device__ float g_K[(size_t)BB * NH * LLEN * DHEAD];     // 32 MB
static __device__ float g_V[(size_t)BB * NH * LLEN * DHEAD];     // 32 MB
static __device__ float g_ctx[(size_t)BB * LLEN * DMODEL];       // 32 MB
static __device__ float g_proj[(size_t)BB * LLEN * DMODEL];      // 32 MB
static __device__ float g_attn[(size_t)BB * NH * LLEN * LLEN];   // 512 MB fallback

// ---------------- tf32 warp-MMA helpers ----------------
__device__ __forceinline__ unsigned f2tf32(float x) {
    unsigned r;
    asm("cvt.rna.tf32.f32 %0, %1;" : "=r"(r) : "f"(x));
    return r;
}

__device__ __forceinline__ void mma_tf32(float* d, const unsigned* a, const unsigned* b) {
    asm volatile(
        "mma.sync.aligned.m16n8k8.row.col.f32.tf32.tf32.f32 "
        "{%0,%1,%2,%3}, {%4,%5,%6,%7}, {%8,%9}, {%0,%1,%2,%3};\n"
        : "+f"(d[0]), "+f"(d[1]), "+f"(d[2]), "+f"(d[3])
        : "r"(a[0]), "r"(a[1]), "r"(a[2]), "r"(a[3]), "r"(b[0]), "r"(b[1]));
}

// =========================================================================
// Kernel 1: fused QKV projection (tf32 MMA).  unchanged.
// =========================================================================
__global__ __launch_bounds__(256) void qkv_mma_kernel(
    const float* __restrict__ X,
    const float* __restrict__ Wq,
    const float* __restrict__ Wk,
    const float* __restrict__ Wv)
{
    __shared__ unsigned As[128][36];
    __shared__ unsigned Bs[128][36];

    const int tid  = threadIdx.x;
    const int warp = tid >> 5, lane = tid & 31;
    const int wm = warp >> 1, wn = warp & 1;
    const int g = lane >> 2, t = lane & 3;

    const int m0 = blockIdx.y * 128;
    const int ng = blockIdx.x * 128;
    const int wsel = ng >> 10;
    const int nl = ng & 1023;
    const float* __restrict__ W = (wsel == 0) ? Wq : (wsel == 1 ? Wk : Wv);

    float acc[2][8][4];
#pragma unroll
    for (int i = 0; i < 2; i++)
#pragma unroll
        for (int j = 0; j < 8; j++)
#pragma unroll
            for (int c = 0; c < 4; c++) acc[i][j][c] = 0.f;

    for (int k0 = 0; k0 < DMODEL; k0 += 32) {
#pragma unroll
        for (int r = 0; r < 4; r++) {
            int idx = tid + r * 256;
            int m = idx >> 3, kq = (idx & 7) * 4;
            const float4 v = *(const float4*)&X[(size_t)(m0 + m) * DMODEL + k0 + kq];
            As[m][kq + 0] = f2tf32(v.x);
            As[m][kq + 1] = f2tf32(v.y);
            As[m][kq + 2] = f2tf32(v.z);
            As[m][kq + 3] = f2tf32(v.w);
        }
#pragma unroll
        for (int r = 0; r < 16; r++) {
            int idx = tid + r * 256;
            int k = idx >> 7, n = idx & 127;
            Bs[n][k] = f2tf32(W[(size_t)(k0 + k) * DMODEL + nl + n]);
        }
        __syncthreads();

#pragma unroll
        for (int ks = 0; ks < 32; ks += 8) {
            unsigned af[2][4], bf[8][2];
#pragma unroll
            for (int i = 0; i < 2; i++) {
                int mr = wm * 32 + i * 16;
                af[i][0] = As[mr + g][ks + t];
                af[i][1] = As[mr + g + 8][ks + t];
                af[i][2] = As[mr + g][ks + t + 4];
                af[i][3] = As[mr + g + 8][ks + t + 4];
            }
#pragma unroll
            for (int j = 0; j < 8; j++) {
                int nr = wn * 64 + j * 8;
                bf[j][0] = Bs[nr + g][ks + t];
                bf[j][1] = Bs[nr + g][ks + t + 4];
            }
#pragma unroll
            for (int i = 0; i < 2; i++)
#pragma unroll
                for (int j = 0; j < 8; j++) mma_tf32(acc[i][j], af[i], bf[j]);
        }
        __syncthreads();
    }

    float* __restrict__ dst = (wsel == 0) ? g_Q : (wsel == 1 ? g_K : g_V);
#pragma unroll
    for (int i = 0; i < 2; i++) {
        int r0 = m0 + wm * 32 + i * 16 + g;
        int b = r0 >> 10, l = r0 & 1023;
#pragma unroll
        for (int j = 0; j < 8; j++) {
            int cl = nl + wn * 64 + j * 8 + 2 * t;
            int h = cl >> 6, d = cl & 63;
            size_t base = ((size_t)(b * NH + h) * LLEN);
            float2 v0 = make_float2(acc[i][j][0], acc[i][j][1]);
            float2 v1 = make_float2(acc[i][j][2], acc[i][j][3]);
            *(float2*)&dst[(base + l) * DHEAD + d] = v0;
            *(float2*)&dst[(base + l + 8) * DHEAD + d] = v1;
        }
    }
}

// =========================================================================
// Kernel 2: FULLY FUSED attention: S = QK^T*scale -> mask -> softmax ->
// write P (required output) -> ctx = P @ V, all in one kernel.
// CTA = 16 Q-rows x 1024 K-cols for one (b,h).  8 warps, each owns 16 cols
// per 128-col block; S strip lives in registers (64 floats/thread).
// Phase B reuses the K smem buffer for V blocks and accumulates ctx[16x64].
// =========================================================================
__global__ __launch_bounds__(256) void fused_attn_kernel(
    const int* __restrict__ mask,
    float* __restrict__ attn_ext)
{
    __shared__ unsigned Qs[16][68];          // 4352 B
    __shared__ unsigned KVs[128][68];        // 34816 B (K blocks, then V blocks)
    __shared__ float    Psm[16][132];        // 8448 B (P block staging)
    __shared__ float    red[16][8];          //  512 B
    float* const KVf = (float*)&KVs[0][0];   // V view (same layout [128][68])

    const int tid  = threadIdx.x;
    const int warp = tid >> 5, lane = tid & 31;
    const int g = lane >> 2, t = lane & 3;

    const int bh = blockIdx.y;
    const int b  = bh / NH, h = bh % NH;
    const int m0 = blockIdx.x * 16;
    const float* __restrict__ Q = g_Q + (size_t)bh * LLEN * DHEAD;
    const float* __restrict__ K = g_K + (size_t)bh * LLEN * DHEAD;
    const float* __restrict__ V = g_V + (size_t)bh * LLEN * DHEAD;

    // load Q strip 16x64 (one float4 per thread)
    {
        int m = tid >> 4, kq = (tid & 15) * 4;
        const float4 v = *(const float4*)&Q[(size_t)(m0 + m) * DHEAD + kq];
        Qs[m][kq + 0] = f2tf32(v.x);
        Qs[m][kq + 1] = f2tf32(v.y);
        Qs[m][kq + 2] = f2tf32(v.z);
        Qs[m][kq + 3] = f2tf32(v.w);
    }

    float acc[8][2][4];
#pragma unroll
    for (int s = 0; s < 8; s++)
#pragma unroll
        for (int j = 0; j < 2; j++)
#pragma unroll
            for (int c = 0; c < 4; c++) acc[s][j][c] = 0.f;

    // ---------------- Phase A: S = Q K^T ----------------
#pragma unroll
    for (int s = 0; s < 8; s++) {
        const int n0 = s * 128;
        __syncthreads();   // Qs visible (s=0) / previous block's MMA reads done
#pragma unroll
        for (int r = 0; r < 8; r++) {
            int idx = tid + r * 256;
            int n = idx >> 4, kq = (idx & 15) * 4;
            const float4 v = *(const float4*)&K[(size_t)(n0 + n) * DHEAD + kq];
            KVs[n][kq + 0] = f2tf32(v.x);
            KVs[n][kq + 1] = f2tf32(v.y);
            KVs[n][kq + 2] = f2tf32(v.z);
            KVs[n][kq + 3] = f2tf32(v.w);
        }
        __syncthreads();

#pragma unroll
        for (int ks = 0; ks < 64; ks += 8) {
            unsigned af[4], bf[2][2];
            af[0] = Qs[g][ks + t];
            af[1] = Qs[g + 8][ks + t];
            af[2] = Qs[g][ks + t + 4];
            af[3] = Qs[g + 8][ks + t + 4];
#pragma unroll
            for (int j = 0; j < 2; j++) {
                int nr = warp * 16 + j * 8;
                bf[j][0] = KVs[nr + g][ks + t];
                bf[j][1] = KVs[nr + g][ks + t + 4];
            }
#pragma unroll
            for (int j = 0; j < 2; j++) mma_tf32(acc[s][j], af, bf[j]);
        }
    }

    // ---------------- scale + mask + row max ----------------
    const float scale = 0.125f;
    const int ql = m0 + g, qh = m0 + g + 8;
    const int* __restrict__ mrl = mask + ((size_t)b * LLEN + ql) * LLEN;
    const int* __restrict__ mrh = mask + ((size_t)b * LLEN + qh) * LLEN;

    float mxl = -3e38f, mxh = -3e38f;
#pragma unroll
    for (int s = 0; s < 8; s++)
#pragma unroll
        for (int j = 0; j < 2; j++) {
            const int col = s * 128 + warp * 16 + j * 8 + 2 * t;
            const int2 mkl = *(const int2*)&mrl[col];
            const int2 mkh = *(const int2*)&mrh[col];
            float* a = acc[s][j];
            a[0] = mkl.x ? -1e9f : a[0] * scale;
            a[1] = mkl.y ? -1e9f : a[1] * scale;
            a[2] = mkh.x ? -1e9f : a[2] * scale;
            a[3] = mkh.y ? -1e9f : a[3] * scale;
            mxl = fmaxf(mxl, fmaxf(a[0], a[1]));
            mxh = fmaxf(mxh, fmaxf(a[2], a[3]));
        }
    mxl = fmaxf(mxl, __shfl_xor_sync(0xffffffffu, mxl, 1));
    mxl = fmaxf(mxl, __shfl_xor_sync(0xffffffffu, mxl, 2));
    mxh = fmaxf(mxh, __shfl_xor_sync(0xffffffffu, mxh, 1));
    mxh = fmaxf(mxh, __shfl_xor_sync(0xffffffffu, mxh, 2));
    __syncthreads();
    if (t == 0) { red[g][warp] = mxl; red[g + 8][warp] = mxh; }
    __syncthreads();
    float Ml = red[g][0], Mh = red[g + 8][0];
#pragma unroll
    for (int w = 1; w < 8; w++) {
        Ml = fmaxf(Ml, red[g][w]);
        Mh = fmaxf(Mh, red[g + 8][w]);
    }
    __syncthreads();

    // ---------------- exp + row sum ----------------
    float sl = 0.f, sh = 0.f;
#pragma unroll
    for (int s = 0; s < 8; s++)
#pragma unroll
        for (int j = 0; j < 2; j++) {
            float* a = acc[s][j];
            a[0] = expf(a[0] - Ml);
            a[1] = expf(a[1] - Ml);
            a[2] = expf(a[2] - Mh);
            a[3] = expf(a[3] - Mh);
            sl += a[0] + a[1];
            sh += a[2] + a[3];
        }
    sl += __shfl_xor_sync(0xffffffffu, sl, 1);
    sl += __shfl_xor_sync(0xffffffffu, sl, 2);
    sh += __shfl_xor_sync(0xffffffffu, sh, 1);
    sh += __shfl_xor_sync(0xffffffffu, sh, 2);
    if (t == 0) { red[g][warp] = sl; red[g + 8][warp] = sh; }
    __syncthreads();
    float Sl = 0.f, Sh = 0.f;
#pragma unroll
    for (int w = 0; w < 8; w++) { Sl += red[g][w]; Sh += red[g + 8][w]; }
    const float invl = 1.0f / Sl, invh = 1.0f / Sh;

    // ---------------- normalize in regs + single-pass P write ----------------
    float* __restrict__ P = attn_ext ? attn_ext : g_attn;
    float* __restrict__ prl = P + ((size_t)bh * LLEN + ql) * LLEN;
    float* __restrict__ prh = P + ((size_t)bh * LLEN + qh) * LLEN;
#pragma unroll
    for (int s = 0; s < 8; s++)
#pragma unroll
        for (int j = 0; j < 2; j++) {
            const int col = s * 128 + warp * 16 + j * 8 + 2 * t;
            float* a = acc[s][j];
            a[0] *= invl; a[1] *= invl; a[2] *= invh; a[3] *= invh;
            *(float2*)&prl[col] = make_float2(a[0], a[1]);
            *(float2*)&prh[col] = make_float2(a[2], a[3]);
        }

    // ---------------- Phase B: ctx = P @ V ----------------
    // warp w accumulates ctx cols [w*8, w*8+8) over k=1024.
    float ctx[4] = {0.f, 0.f, 0.f, 0.f};
    const int n0w = warp * 8;

#pragma unroll
    for (int s = 0; s < 8; s++) {
        __syncthreads();   // prior iteration's reads of Psm/KVf done
        // stage normalized P block (16x128): warp w writes its 16 cols
#pragma unroll
        for (int j = 0; j < 2; j++) {
            const int c = warp * 16 + j * 8 + 2 * t;
            const float* a = acc[s][j];
            Psm[g][c] = a[0];     Psm[g][c + 1] = a[1];
            Psm[g + 8][c] = a[2]; Psm[g + 8][c + 1] = a[3];
        }
        // stage V block (128 rows x 64 cols) into KVf[128][68]
#pragma unroll
        for (int r = 0; r < 8; r++) {
            int idx = tid + r * 256;
            int kr = idx >> 4, c4 = (idx & 15) * 4;
            const float4 v = *(const float4*)&V[(size_t)(s * 128 + kr) * DHEAD + c4];
            *(float4*)&KVf[kr * 68 + c4] = v;
        }
        __syncthreads();

#pragma unroll
        for (int ks = 0; ks < 128; ks += 8) {
            unsigned af[4], bf[2];
            af[0] = f2tf32(Psm[g][ks + t]);
            af[1] = f2tf32(Psm[g + 8][ks + t]);
            af[2] = f2tf32(Psm[g][ks + t + 4]);
            af[3] = f2tf32(Psm[g + 8][ks + t + 4]);
            bf[0] = f2tf32(KVf[(ks + t) * 68 + n0w + g]);
            bf[1] = f2tf32(KVf[(ks + t + 4) * 68 + n0w + g]);
            mma_tf32(ctx, af, bf);
        }
    }

    // write ctx: rows m0+g / m0+g+8, cols h*64 + w*8 + 2t (+1)
    {
        size_t roff = ((size_t)(b * LLEN + m0 + g)) * DMODEL + h * 64 + n0w + 2 * t;
        *(float2*)&g_ctx[roff] = make_float2(ctx[0], ctx[1]);
        size_t roff2 = ((size_t)(b * LLEN + m0 + g + 8)) * DMODEL + h * 64 + n0w + 2 * t;
        *(float2*)&g_ctx[roff2] = make_float2(ctx[2], ctx[3]);
    }
}

// =========================================================================
// Kernel 3: output projection (tf32 MMA).  unchanged.
// =========================================================================
__global__ __launch_bounds__(256) void proj_mma_kernel(const float* __restrict__ Wo)
{
    __shared__ unsigned As[128][36];
    __shared__ unsigned Bs[128][36];

    const int tid  = threadIdx.x;
    const int warp = tid >> 5, lane = tid & 31;
    const int wm = warp >> 1, wn = warp & 1;
    const int g = lane >> 2, t = lane & 3;

    const int m0 = blockIdx.y * 128;
    const int n0 = blockIdx.x * 128;

    float acc[2][8][4];
#pragma unroll
    for (int i = 0; i < 2; i++)
#pragma unroll
        for (int j = 0; j < 8; j++)
#pragma unroll
            for (int c = 0; c < 4; c++) acc[i][j][c] = 0.f;

    for (int k0 = 0; k0 < DMODEL; k0 += 32) {
#pragma unroll
        for (int r = 0; r < 4; r++) {
            int idx = tid + r * 256;
            int m = idx >> 3, kq = (idx & 7) * 4;
            const float4 v = *(const float4*)&g_ctx[(size_t)(m0 + m) * DMODEL + k0 + kq];
            As[m][kq + 0] = f2tf32(v.x);
            As[m][kq + 1] = f2tf32(v.y);
            As[m][kq + 2] = f2tf32(v.z);
            As[m][kq + 3] = f2tf32(v.w);
        }
#pragma unroll
        for (int r = 0; r < 16; r++) {
            int idx = tid + r * 256;
            int k = idx >> 7, n = idx & 127;
            Bs[n][k] = f2tf32(Wo[(size_t)(k0 + k) * DMODEL + n0 + n]);
        }
        __syncthreads();

#pragma unroll
        for (int ks = 0; ks < 32; ks += 8) {
            unsigned af[2][4], bf[8][2];
#pragma unroll
            for (int i = 0; i < 2; i++) {
                int mr = wm * 32 + i * 16;
                af[i][0] = As[mr + g][ks + t];
                af[i][1] = As[mr + g + 8][ks + t];
                af[i][2] = As[mr + g][ks + t + 4];
                af[i][3] = As[mr + g + 8][ks + t + 4];
            }
#pragma unroll
            for (int j = 0; j < 8; j++) {
                int nr = wn * 64 + j * 8;
                bf[j][0] = Bs[nr + g][ks + t];
                bf[j][1] = Bs[nr + g][ks + t + 4];
            }
#pragma unroll
            for (int i = 0; i < 2; i++)
#pragma unroll
                for (int j = 0; j < 8; j++) mma_tf32(acc[i][j], af[i], bf[j]);
        }
        __syncthreads();
    }

#pragma unroll
    for (int i = 0; i < 2; i++) {
        int r0 = m0 + wm * 32 + i * 16 + g;
#pragma unroll
        for (int j = 0; j < 8; j++) {
            int c = n0 + wn * 64 + j * 8 + 2 * t;
            float2 v0 = make_float2(acc[i][j][0], acc[i][j][1]);
            float2 v1 = make_float2(acc[i][j][2], acc[i][j][3]);
            *(float2*)&g_proj[(size_t)r0 * DMODEL + c] = v0;
            *(float2*)&g_proj[(size_t)(r0 + 8) * DMODEL + c] = v1;
        }
    }
}

// =========================================================================
// Kernel 4: residual + LayerNorm (unchanged).
// =========================================================================
__global__ void ln_kernel(const float* __restrict__ X,
                          const float* __restrict__ gamma,
                          const float* __restrict__ beta,
                          float* __restrict__ out)
{
    const int row = blockIdx.x;
    const int tid = threadIdx.x;
    const float* __restrict__ pr = g_proj + (size_t)row * DMODEL;
    const float* __restrict__ xr = X + (size_t)row * DMODEL;

    float4 p = reinterpret_cast<const float4*>(pr)[tid];
    float4 x = reinterpret_cast<const float4*>(xr)[tid];
    float y0 = p.x + x.x, y1 = p.y + x.y, y2 = p.z + x.z, y3 = p.w + x.w;

    __shared__ float red[8];
    float s = y0 + y1 + y2 + y3;
#pragma unroll
    for (int o = 16; o > 0; o >>= 1) s += __shfl_xor_sync(0xffffffffu, s, o);
    if ((tid & 31) == 0) red[tid >> 5] = s;
    __syncthreads();
    float tot = red[0];
#pragma unroll
    for (int w = 1; w < 8; w++) tot += red[w];
    const float mu = tot * (1.0f / DMODEL);
    __syncthreads();

    float d0 = y0 - mu, d1 = y1 - mu, d2 = y2 - mu, d3 = y3 - mu;
    float sq = d0 * d0 + d1 * d1 + d2 * d2 + d3 * d3;
#pragma unroll
    for (int o = 16; o > 0; o >>= 1) sq += __shfl_xor_sync(0xffffffffu, sq, o);
    if ((tid & 31) == 0) red[tid >> 5] = sq;
    __syncthreads();
    float tot2 = red[0];
#pragma unroll
    for (int w = 1; w < 8; w++) tot2 += red[w];
    const float var = tot2 * (1.0f / DMODEL);
    const float inv = rsqrtf(var + 1e-6f);

    const int c = tid * 4;
    float* __restrict__ orow = out + (size_t)row * DMODEL;
    orow[c + 0] = d0 * inv * gamma[c + 0] + beta[c + 0];
    orow[c + 1] = d1 * inv * gamma[c + 1] + beta[c + 1];
    orow[c + 2] = d2 * inv * gamma[c + 2] + beta[c + 2];
    orow[c + 3] = d3 * inv * gamma[c + 3] + beta[c + 3];
}

// =========================================================================
extern "C" void kernel_launch(void* const* d_in, const int* in_sizes, int n_in,
                              void* d_out, int out_size)
{
    const float* X     = (const float*)d_in[0];
    const int*   mask  = (const int*)d_in[1];
    const float* Wq    = (const float*)d_in[2];
    const float* Wk    = (const float*)d_in[3];
    const float* Wv    = (const float*)d_in[4];
    const float* Wo    = (const float*)d_in[5];
    const float* gamma = (const float*)d_in[6];
    const float* beta  = (const float*)d_in[7];
    float* out = (float*)d_out;

    const long long LN_N   = (long long)BB * LLEN * DMODEL;
    const long long ATTN_N = (long long)BB * NH * LLEN * LLEN;
    float* attn_ptr = ((long long)out_size >= LN_N + ATTN_N) ? (out + LN_N) : nullptr;

    qkv_mma_kernel<<<dim3(24, 64), 256>>>(X, Wq, Wk, Wv);
    fused_attn_kernel<<<dim3(64, BB * NH), 256>>>(mask, attn_ptr);
    proj_mma_kernel<<<dim3(8, 64), 256>>>(Wo);
    ln_kernel<<<BB * LLEN, 256>>>(X, gamma, beta, out);
}

// round 5
// speedup vs baseline: 1.2236x; 1.2236x over previous
#include <cuda_runtime.h>
#include <math.h>

#define BB 8
#define LLEN 1024
#define DMODEL 1024
#define NH 16
#define DHEAD 64

// ---------------- static scratch (no allocations allowed) ----------------
static __device__ float g_Q[(size_t)BB * NH * LLEN * DHEAD];     // 32 MB
static __device__ float g_K[(size_t)BB * NH * LLEN * DHEAD];     // 32 MB
static __device__ float g_V[(size_t)BB * NH * LLEN * DHEAD];     // 32 MB
static __device__ float g_ctx[(size_t)BB * LLEN * DMODEL];       // 32 MB
static __device__ float g_proj[(size_t)BB * LLEN * DMODEL];      // 32 MB
static __device__ float g_attn[(size_t)BB * NH * LLEN * LLEN];   // 512 MB fallback

// ---------------- tf32 warp-MMA helpers ----------------
__device__ __forceinline__ unsigned f2tf32(float x) {
    unsigned r;
    asm("cvt.rna.tf32.f32 %0, %1;" : "=r"(r) : "f"(x));
    return r;
}

__device__ __forceinline__ void mma_tf32(float* d, const unsigned* a, const unsigned* b) {
    asm volatile(
        "mma.sync.aligned.m16n8k8.row.col.f32.tf32.tf32.f32 "
        "{%0,%1,%2,%3}, {%4,%5,%6,%7}, {%8,%9}, {%0,%1,%2,%3};\n"
        : "+f"(d[0]), "+f"(d[1]), "+f"(d[2]), "+f"(d[3])
        : "r"(a[0]), "r"(a[1]), "r"(a[2]), "r"(a[3]), "r"(b[0]), "r"(b[1]));
}

__device__ __forceinline__ void cp16(void* smem_dst, const void* gsrc) {
    unsigned s = (unsigned)__cvta_generic_to_shared(smem_dst);
    asm volatile("cp.async.ca.shared.global [%0], [%1], 16;\n" :: "r"(s), "l"(gsrc));
}
__device__ __forceinline__ void cp_commit() {
    asm volatile("cp.async.commit_group;\n");
}
template <int N>
__device__ __forceinline__ void cp_wait() {
    asm volatile("cp.async.wait_group %0;\n" :: "n"(N));
}

// =========================================================================
// Kernel 1: fused QKV projection, cp.async 2-stage pipeline.
// M=8192, N=3072, K=1024.  BM=BN=128, BK=16.
// A staged [m][k] (stride 20), B staged in gmem layout [k][n] (stride 136).
// 8 warps: 4(m) x 2(n), warp tile 32x64.
// =========================================================================
__global__ __launch_bounds__(256) void qkv_mma_kernel(
    const float* __restrict__ X,
    const float* __restrict__ Wq,
    const float* __restrict__ Wk,
    const float* __restrict__ Wv)
{
    __shared__ float As[2][128][20];   // 20480 B
    __shared__ float Bs[2][16][136];   // 17408 B

    const int tid  = threadIdx.x;
    const int warp = tid >> 5, lane = tid & 31;
    const int wm = warp >> 1, wn = warp & 1;
    const int g = lane >> 2, t = lane & 3;

    const int m0 = blockIdx.y * 128;
    const int ng = blockIdx.x * 128;
    const int wsel = ng >> 10;
    const int nl = ng & 1023;
    const float* __restrict__ W = (wsel == 0) ? Wq : (wsel == 1 ? Wk : Wv);

    // cp.async assignments: A = 512 chunks (m=c>>2, ch=c&3); B = 512 (k=c>>5, ch=c&31)
    const int am0 = (tid * 2) >> 2,      ach0 = ((tid * 2) & 3) * 4;
    const int am1 = (tid * 2 + 1) >> 2,  ach1 = ((tid * 2 + 1) & 3) * 4;
    const int bk0 = (tid * 2) >> 5,      bch0 = ((tid * 2) & 31) * 4;
    const int bk1 = (tid * 2 + 1) >> 5,  bch1 = ((tid * 2 + 1) & 31) * 4;

    float acc[2][8][4];
#pragma unroll
    for (int i = 0; i < 2; i++)
#pragma unroll
        for (int j = 0; j < 8; j++)
#pragma unroll
            for (int c = 0; c < 4; c++) acc[i][j][c] = 0.f;

    // prologue: stage 0
    cp16(&As[0][am0][ach0], &X[(size_t)(m0 + am0) * DMODEL + ach0]);
    cp16(&As[0][am1][ach1], &X[(size_t)(m0 + am1) * DMODEL + ach1]);
    cp16(&Bs[0][bk0][bch0], &W[(size_t)bk0 * DMODEL + nl + bch0]);
    cp16(&Bs[0][bk1][bch1], &W[(size_t)bk1 * DMODEL + nl + bch1]);
    cp_commit();

    const int NIT = DMODEL / 16;
    for (int it = 0; it < NIT; it++) {
        const int buf = it & 1;
        if (it + 1 < NIT) {
            const int k0 = (it + 1) * 16;
            cp16(&As[buf ^ 1][am0][ach0], &X[(size_t)(m0 + am0) * DMODEL + k0 + ach0]);
            cp16(&As[buf ^ 1][am1][ach1], &X[(size_t)(m0 + am1) * DMODEL + k0 + ach1]);
            cp16(&Bs[buf ^ 1][bk0][bch0], &W[(size_t)(k0 + bk0) * DMODEL + nl + bch0]);
            cp16(&Bs[buf ^ 1][bk1][bch1], &W[(size_t)(k0 + bk1) * DMODEL + nl + bch1]);
            cp_commit();
            cp_wait<1>();
        } else {
            cp_wait<0>();
        }
        __syncthreads();

#pragma unroll
        for (int ks = 0; ks < 16; ks += 8) {
            unsigned af[2][4], bf[8][2];
#pragma unroll
            for (int i = 0; i < 2; i++) {
                int mr = wm * 32 + i * 16;
                af[i][0] = f2tf32(As[buf][mr + g][ks + t]);
                af[i][1] = f2tf32(As[buf][mr + g + 8][ks + t]);
                af[i][2] = f2tf32(As[buf][mr + g][ks + t + 4]);
                af[i][3] = f2tf32(As[buf][mr + g + 8][ks + t + 4]);
            }
#pragma unroll
            for (int j = 0; j < 8; j++) {
                int nr = wn * 64 + j * 8;
                bf[j][0] = f2tf32(Bs[buf][ks + t][nr + g]);
                bf[j][1] = f2tf32(Bs[buf][ks + t + 4][nr + g]);
            }
#pragma unroll
            for (int i = 0; i < 2; i++)
#pragma unroll
                for (int j = 0; j < 8; j++) mma_tf32(acc[i][j], af[i], bf[j]);
        }
        __syncthreads();
    }

    float* __restrict__ dst = (wsel == 0) ? g_Q : (wsel == 1 ? g_K : g_V);
#pragma unroll
    for (int i = 0; i < 2; i++) {
        int r0 = m0 + wm * 32 + i * 16 + g;
        int b = r0 >> 10, l = r0 & 1023;
#pragma unroll
        for (int j = 0; j < 8; j++) {
            int cl = nl + wn * 64 + j * 8 + 2 * t;
            int h = cl >> 6, d = cl & 63;
            size_t base = ((size_t)(b * NH + h) * LLEN);
            float2 v0 = make_float2(acc[i][j][0], acc[i][j][1]);
            float2 v1 = make_float2(acc[i][j][2], acc[i][j][3]);
            *(float2*)&dst[(base + l) * DHEAD + d] = v0;
            *(float2*)&dst[(base + l + 8) * DHEAD + d] = v1;
        }
    }
}

// =========================================================================
// Kernel 2: FUSED scores + mask + softmax (R3 version, __expf).
// One CTA = 16 Q-rows x 1024 K-cols for one (b,h); S strip in registers;
// single-pass normalized P write.
// =========================================================================
__global__ __launch_bounds__(256) void fused_attn_kernel(
    const int* __restrict__ mask,
    float* __restrict__ attn_ext)
{
    __shared__ unsigned Qs[16][68];
    __shared__ unsigned Ks[128][68];
    __shared__ float red[16][8];

    const int tid  = threadIdx.x;
    const int warp = tid >> 5, lane = tid & 31;
    const int g = lane >> 2, t = lane & 3;

    const int bh = blockIdx.y;
    const int b  = bh / NH;
    const int m0 = blockIdx.x * 16;
    const float* __restrict__ Q = g_Q + (size_t)bh * LLEN * DHEAD;
    const float* __restrict__ K = g_K + (size_t)bh * LLEN * DHEAD;

    {
        int m = tid >> 4, kq = (tid & 15) * 4;
        const float4 v = *(const float4*)&Q[(size_t)(m0 + m) * DHEAD + kq];
        Qs[m][kq + 0] = f2tf32(v.x);
        Qs[m][kq + 1] = f2tf32(v.y);
        Qs[m][kq + 2] = f2tf32(v.z);
        Qs[m][kq + 3] = f2tf32(v.w);
    }

    float acc[8][2][4];
#pragma unroll
    for (int s = 0; s < 8; s++)
#pragma unroll
        for (int j = 0; j < 2; j++)
#pragma unroll
            for (int c = 0; c < 4; c++) acc[s][j][c] = 0.f;

#pragma unroll
    for (int s = 0; s < 8; s++) {
        const int n0 = s * 128;
        __syncthreads();
#pragma unroll
        for (int r = 0; r < 8; r++) {
            int idx = tid + r * 256;
            int n = idx >> 4, kq = (idx & 15) * 4;
            const float4 v = *(const float4*)&K[(size_t)(n0 + n) * DHEAD + kq];
            Ks[n][kq + 0] = f2tf32(v.x);
            Ks[n][kq + 1] = f2tf32(v.y);
            Ks[n][kq + 2] = f2tf32(v.z);
            Ks[n][kq + 3] = f2tf32(v.w);
        }
        __syncthreads();

#pragma unroll
        for (int ks = 0; ks < 64; ks += 8) {
            unsigned af[4], bf[2][2];
            af[0] = Qs[g][ks + t];
            af[1] = Qs[g + 8][ks + t];
            af[2] = Qs[g][ks + t + 4];
            af[3] = Qs[g + 8][ks + t + 4];
#pragma unroll
            for (int j = 0; j < 2; j++) {
                int nr = warp * 16 + j * 8;
                bf[j][0] = Ks[nr + g][ks + t];
                bf[j][1] = Ks[nr + g][ks + t + 4];
            }
#pragma unroll
            for (int j = 0; j < 2; j++) mma_tf32(acc[s][j], af, bf[j]);
        }
    }

    // ---- scale + mask + row max ----
    const float scale = 0.125f;
    const int ql = m0 + g, qh = m0 + g + 8;
    const int* __restrict__ mrl = mask + ((size_t)b * LLEN + ql) * LLEN;
    const int* __restrict__ mrh = mask + ((size_t)b * LLEN + qh) * LLEN;

    float mxl = -3e38f, mxh = -3e38f;
#pragma unroll
    for (int s = 0; s < 8; s++)
#pragma unroll
        for (int j = 0; j < 2; j++) {
            const int col = s * 128 + warp * 16 + j * 8 + 2 * t;
            const int2 mkl = *(const int2*)&mrl[col];
            const int2 mkh = *(const int2*)&mrh[col];
            float* a = acc[s][j];
            a[0] = mkl.x ? -1e9f : a[0] * scale;
            a[1] = mkl.y ? -1e9f : a[1] * scale;
            a[2] = mkh.x ? -1e9f : a[2] * scale;
            a[3] = mkh.y ? -1e9f : a[3] * scale;
            mxl = fmaxf(mxl, fmaxf(a[0], a[1]));
            mxh = fmaxf(mxh, fmaxf(a[2], a[3]));
        }
    mxl = fmaxf(mxl, __shfl_xor_sync(0xffffffffu, mxl, 1));
    mxl = fmaxf(mxl, __shfl_xor_sync(0xffffffffu, mxl, 2));
    mxh = fmaxf(mxh, __shfl_xor_sync(0xffffffffu, mxh, 1));
    mxh = fmaxf(mxh, __shfl_xor_sync(0xffffffffu, mxh, 2));
    __syncthreads();
    if (t == 0) { red[g][warp] = mxl; red[g + 8][warp] = mxh; }
    __syncthreads();
    float Ml = red[g][0], Mh = red[g + 8][0];
#pragma unroll
    for (int w = 1; w < 8; w++) {
        Ml = fmaxf(Ml, red[g][w]);
        Mh = fmaxf(Mh, red[g + 8][w]);
    }
    __syncthreads();

    // ---- exp + row sum ----
    float sl = 0.f, sh = 0.f;
#pragma unroll
    for (int s = 0; s < 8; s++)
#pragma unroll
        for (int j = 0; j < 2; j++) {
            float* a = acc[s][j];
            a[0] = __expf(a[0] - Ml);
            a[1] = __expf(a[1] - Ml);
            a[2] = __expf(a[2] - Mh);
            a[3] = __expf(a[3] - Mh);
            sl += a[0] + a[1];
            sh += a[2] + a[3];
        }
    sl += __shfl_xor_sync(0xffffffffu, sl, 1);
    sl += __shfl_xor_sync(0xffffffffu, sl, 2);
    sh += __shfl_xor_sync(0xffffffffu, sh, 1);
    sh += __shfl_xor_sync(0xffffffffu, sh, 2);
    if (t == 0) { red[g][warp] = sl; red[g + 8][warp] = sh; }
    __syncthreads();
    float Sl = 0.f, Sh = 0.f;
#pragma unroll
    for (int w = 0; w < 8; w++) { Sl += red[g][w]; Sh += red[g + 8][w]; }
    const float invl = 1.0f / Sl, invh = 1.0f / Sh;

    // ---- normalized single-pass P write ----
    float* __restrict__ P = attn_ext ? attn_ext : g_attn;
    float* __restrict__ prl = P + ((size_t)bh * LLEN + ql) * LLEN;
    float* __restrict__ prh = P + ((size_t)bh * LLEN + qh) * LLEN;
#pragma unroll
    for (int s = 0; s < 8; s++)
#pragma unroll
        for (int j = 0; j < 2; j++) {
            const int col = s * 128 + warp * 16 + j * 8 + 2 * t;
            const float* a = acc[s][j];
            *(float2*)&prl[col] = make_float2(a[0] * invl, a[1] * invl);
            *(float2*)&prh[col] = make_float2(a[2] * invh, a[3] * invh);
        }
}

// =========================================================================
// Kernel 3: context = P @ V (tf32 MMA, cp.async 2-stage).  R3 version.
// =========================================================================
__global__ __launch_bounds__(256) void pv_mma_kernel(const float* __restrict__ attn_ext)
{
    __shared__ float Ps[2][128][20];
    __shared__ float Vs[2][16][72];

    const int tid  = threadIdx.x;
    const int warp = tid >> 5, lane = tid & 31;
    const int wm = warp >> 1, wn = warp & 1;
    const int g = lane >> 2, t = lane & 3;

    const int bh = blockIdx.y;
    const int m0 = blockIdx.x * 128;
    const float* __restrict__ P =
        (attn_ext ? attn_ext : (const float*)g_attn) + (size_t)bh * LLEN * LLEN;
    const float* __restrict__ V = g_V + (size_t)bh * LLEN * DHEAD;

    const int prow = tid >> 2, pc4 = (tid & 3) * 4;
    const int vrow = tid >> 4, vc4 = (tid & 15) * 4;

    float acc[2][4][4];
#pragma unroll
    for (int i = 0; i < 2; i++)
#pragma unroll
        for (int j = 0; j < 4; j++)
#pragma unroll
            for (int c = 0; c < 4; c++) acc[i][j][c] = 0.f;

    {
        cp16(&Ps[0][prow][pc4],      &P[(size_t)(m0 + prow) * LLEN + pc4]);
        cp16(&Ps[0][prow + 64][pc4], &P[(size_t)(m0 + prow + 64) * LLEN + pc4]);
        cp16(&Vs[0][vrow][vc4],      &V[(size_t)vrow * DHEAD + vc4]);
        cp_commit();
    }

    const int NIT = LLEN / 16;
    for (int it = 0; it < NIT; it++) {
        const int buf = it & 1;
        if (it + 1 < NIT) {
            const int k0 = (it + 1) * 16;
            cp16(&Ps[buf ^ 1][prow][pc4],      &P[(size_t)(m0 + prow) * LLEN + k0 + pc4]);
            cp16(&Ps[buf ^ 1][prow + 64][pc4], &P[(size_t)(m0 + prow + 64) * LLEN + k0 + pc4]);
            cp16(&Vs[buf ^ 1][vrow][vc4],      &V[(size_t)(k0 + vrow) * DHEAD + vc4]);
            cp_commit();
            cp_wait<1>();
        } else {
            cp_wait<0>();
        }
        __syncthreads();

#pragma unroll
        for (int ks = 0; ks < 16; ks += 8) {
            unsigned af[2][4], bf[4][2];
#pragma unroll
            for (int i = 0; i < 2; i++) {
                int mr = wm * 32 + i * 16;
                af[i][0] = f2tf32(Ps[buf][mr + g][ks + t]);
                af[i][1] = f2tf32(Ps[buf][mr + g + 8][ks + t]);
                af[i][2] = f2tf32(Ps[buf][mr + g][ks + t + 4]);
                af[i][3] = f2tf32(Ps[buf][mr + g + 8][ks + t + 4]);
            }
#pragma unroll
            for (int j = 0; j < 4; j++) {
                int nr = wn * 32 + j * 8;
                bf[j][0] = f2tf32(Vs[buf][ks + t][nr + g]);
                bf[j][1] = f2tf32(Vs[buf][ks + t + 4][nr + g]);
            }
#pragma unroll
            for (int i = 0; i < 2; i++)
#pragma unroll
                for (int j = 0; j < 4; j++) mma_tf32(acc[i][j], af[i], bf[j]);
        }
        __syncthreads();
    }

    const int b = bh / NH, h = bh % NH;
#pragma unroll
    for (int i = 0; i < 2; i++) {
        int l0 = m0 + wm * 32 + i * 16 + g;
#pragma unroll
        for (int j = 0; j < 4; j++) {
            int d = wn * 32 + j * 8 + 2 * t;
            float2 v0 = make_float2(acc[i][j][0], acc[i][j][1]);
            float2 v1 = make_float2(acc[i][j][2], acc[i][j][3]);
            *(float2*)&g_ctx[((size_t)(b * LLEN + l0)) * DMODEL + h * 64 + d] = v0;
            *(float2*)&g_ctx[((size_t)(b * LLEN + l0 + 8)) * DMODEL + h * 64 + d] = v1;
        }
    }
}

// =========================================================================
// Kernel 4: output projection, cp.async 2-stage pipeline (same as qkv).
// =========================================================================
__global__ __launch_bounds__(256) void proj_mma_kernel(const float* __restrict__ Wo)
{
    __shared__ float As[2][128][20];
    __shared__ float Bs[2][16][136];

    const int tid  = threadIdx.x;
    const int warp = tid >> 5, lane = tid & 31;
    const int wm = warp >> 1, wn = warp & 1;
    const int g = lane >> 2, t = lane & 3;

    const int m0 = blockIdx.y * 128;
    const int n0 = blockIdx.x * 128;

    const int am0 = (tid * 2) >> 2,      ach0 = ((tid * 2) & 3) * 4;
    const int am1 = (tid * 2 + 1) >> 2,  ach1 = ((tid * 2 + 1) & 3) * 4;
    const int bk0 = (tid * 2) >> 5,      bch0 = ((tid * 2) & 31) * 4;
    const int bk1 = (tid * 2 + 1) >> 5,  bch1 = ((tid * 2 + 1) & 31) * 4;

    float acc[2][8][4];
#pragma unroll
    for (int i = 0; i < 2; i++)
#pragma unroll
        for (int j = 0; j < 8; j++)
#pragma unroll
            for (int c = 0; c < 4; c++) acc[i][j][c] = 0.f;

    cp16(&As[0][am0][ach0], &g_ctx[(size_t)(m0 + am0) * DMODEL + ach0]);
    cp16(&As[0][am1][ach1], &g_ctx[(size_t)(m0 + am1) * DMODEL + ach1]);
    cp16(&Bs[0][bk0][bch0], &Wo[(size_t)bk0 * DMODEL + n0 + bch0]);
    cp16(&Bs[0][bk1][bch1], &Wo[(size_t)bk1 * DMODEL + n0 + bch1]);
    cp_commit();

    const int NIT = DMODEL / 16;
    for (int it = 0; it < NIT; it++) {
        const int buf = it & 1;
        if (it + 1 < NIT) {
            const int k0 = (it + 1) * 16;
            cp16(&As[buf ^ 1][am0][ach0], &g_ctx[(size_t)(m0 + am0) * DMODEL + k0 + ach0]);
            cp16(&As[buf ^ 1][am1][ach1], &g_ctx[(size_t)(m0 + am1) * DMODEL + k0 + ach1]);
            cp16(&Bs[buf ^ 1][bk0][bch0], &Wo[(size_t)(k0 + bk0) * DMODEL + n0 + bch0]);
            cp16(&Bs[buf ^ 1][bk1][bch1], &Wo[(size_t)(k0 + bk1) * DMODEL + n0 + bch1]);
            cp_commit();
            cp_wait<1>();
        } else {
            cp_wait<0>();
        }
        __syncthreads();

#pragma unroll
        for (int ks = 0; ks < 16; ks += 8) {
            unsigned af[2][4], bf[8][2];
#pragma unroll
            for (int i = 0; i < 2; i++) {
                int mr = wm * 32 + i * 16;
                af[i][0] = f2tf32(As[buf][mr + g][ks + t]);
                af[i][1] = f2tf32(As[buf][mr + g + 8][ks + t]);
                af[i][2] = f2tf32(As[buf][mr + g][ks + t + 4]);
                af[i][3] = f2tf32(As[buf][mr + g + 8][ks + t + 4]);
            }
#pragma unroll
            for (int j = 0; j < 8; j++) {
                int nr = wn * 64 + j * 8;
                bf[j][0] = f2tf32(Bs[buf][ks + t][nr + g]);
                bf[j][1] = f2tf32(Bs[buf][ks + t + 4][nr + g]);
            }
#pragma unroll
            for (int i = 0; i < 2; i++)
#pragma unroll
                for (int j = 0; j < 8; j++) mma_tf32(acc[i][j], af[i], bf[j]);
        }
        __syncthreads();
    }

#pragma unroll
    for (int i = 0; i < 2; i++) {
        int r0 = m0 + wm * 32 + i * 16 + g;
#pragma unroll
        for (int j = 0; j < 8; j++) {
            int c = n0 + wn * 64 + j * 8 + 2 * t;
            float2 v0 = make_float2(acc[i][j][0], acc[i][j][1]);
            float2 v1 = make_float2(acc[i][j][2], acc[i][j][3]);
            *(float2*)&g_proj[(size_t)r0 * DMODEL + c] = v0;
            *(float2*)&g_proj[(size_t)(r0 + 8) * DMODEL + c] = v1;
        }
    }
}

// =========================================================================
// Kernel 5: residual + LayerNorm (unchanged).
// =========================================================================
__global__ void ln_kernel(const float* __restrict__ X,
                          const float* __restrict__ gamma,
                          const float* __restrict__ beta,
                          float* __restrict__ out)
{
    const int row = blockIdx.x;
    const int tid = threadIdx.x;
    const float* __restrict__ pr = g_proj + (size_t)row * DMODEL;
    const float* __restrict__ xr = X + (size_t)row * DMODEL;

    float4 p = reinterpret_cast<const float4*>(pr)[tid];
    float4 x = reinterpret_cast<const float4*>(xr)[tid];
    float y0 = p.x + x.x, y1 = p.y + x.y, y2 = p.z + x.z, y3 = p.w + x.w;

    __shared__ float red[8];
    float s = y0 + y1 + y2 + y3;
#pragma unroll
    for (int o = 16; o > 0; o >>= 1) s += __shfl_xor_sync(0xffffffffu, s, o);
    if ((tid & 31) == 0) red[tid >> 5] = s;
    __syncthreads();
    float tot = red[0];
#pragma unroll
    for (int w = 1; w < 8; w++) tot += red[w];
    const float mu = tot * (1.0f / DMODEL);
    __syncthreads();

    float d0 = y0 - mu, d1 = y1 - mu, d2 = y2 - mu, d3 = y3 - mu;
    float sq = d0 * d0 + d1 * d1 + d2 * d2 + d3 * d3;
#pragma unroll
    for (int o = 16; o > 0; o >>= 1) sq += __shfl_xor_sync(0xffffffffu, sq, o);
    if ((tid & 31) == 0) red[tid >> 5] = sq;
    __syncthreads();
    float tot2 = red[0];
#pragma unroll
    for (int w = 1; w < 8; w++) tot2 += red[w];
    const float var = tot2 * (1.0f / DMODEL);
    const float inv = rsqrtf(var + 1e-6f);

    const int c = tid * 4;
    float* __restrict__ orow = out + (size_t)row * DMODEL;
    orow[c + 0] = d0 * inv * gamma[c + 0] + beta[c + 0];
    orow[c + 1] = d1 * inv * gamma[c + 1] + beta[c + 1];
    orow[c + 2] = d2 * inv * gamma[c + 2] + beta[c + 2];
    orow[c + 3] = d3 * inv * gamma[c + 3] + beta[c + 3];
}

// =========================================================================
extern "C" void kernel_launch(void* const* d_in, const int* in_sizes, int n_in,
                              void* d_out, int out_size)
{
    const float* X     = (const float*)d_in[0];
    const int*   mask  = (const int*)d_in[1];
    const float* Wq    = (const float*)d_in[2];
    const float* Wk    = (const float*)d_in[3];
    const float* Wv    = (const float*)d_in[4];
    const float* Wo    = (const float*)d_in[5];
    const float* gamma = (const float*)d_in[6];
    const float* beta  = (const float*)d_in[7];
    float* out = (float*)d_out;

    const long long LN_N   = (long long)BB * LLEN * DMODEL;
    const long long ATTN_N = (long long)BB * NH * LLEN * LLEN;
    float* attn_ptr = ((long long)out_size >= LN_N + ATTN_N) ? (out + LN_N) : nullptr;

    qkv_mma_kernel<<<dim3(24, 64), 256>>>(X, Wq, Wk, Wv);
    fused_attn_kernel<<<dim3(64, BB * NH), 256>>>(mask, attn_ptr);
    pv_mma_kernel<<<dim3(8, BB * NH), 256>>>(attn_ptr);
    proj_mma_kernel<<<dim3(8, 64), 256>>>(Wo);
    ln_kernel<<<BB * LLEN, 256>>>(X, gamma, beta, out);
}